// round 9
// baseline (speedup 1.0000x reference)
#include <cuda_runtime.h>
#include <math.h>

#define B_ 1024
#define N_ 50000
#define D_ 256
#define NV4 (N_ / 4)        // 12500 float4 per row
#define WPR 25              // warps per row: 24 full segs of 512 + 1 seg of 212
#define SEG 512             // float4 per full warp segment
#define P1_TPB 256
#define P1_GRID (B_ * WPR / 8)   // 3200 blocks
#define P2_BLOCKS 128
#define P2_TPB 256

// Per-row partials: 0..2 sumexp(merged,text,rec), 3..5 dot, 6 sum(x)
__device__ double g_row[B_][7];
// Staged per-block partials (plain stores, overwritten every call -> no reset)
__device__ double g_dt[P2_BLOCKS][3];   // KLD1 / KLD2 / wasserstein partials
__device__ double g_fix[32][3];         // BCE correction partials (blocks 0..31)
__device__ unsigned int g_cnt;

__device__ __forceinline__ float sum_exp4(float4 v) {
    return __expf(v.x) + __expf(v.y) + __expf(v.z) + __expf(v.w);
}
__device__ __forceinline__ float dot4(float4 a, float4 b) {
    return a.x * b.x + a.y * b.y + a.z * b.z + a.w * b.w;
}

// Pass 1 (byte-identical to the proven round-3 kernel): warp-centric,
// barrier-free streaming reduce over the 3 logits matrices + x.
__global__ __launch_bounds__(P1_TPB, 4)
void pass1_kernel(const float4* __restrict__ recon,
                  const float4* __restrict__ xmat,
                  const float4* __restrict__ text,
                  const float4* __restrict__ rec)
{
    const int lane = threadIdx.x & 31;
    const int gw   = (blockIdx.x * P1_TPB + threadIdx.x) >> 5;  // global warp id
    const int row  = gw / WPR;
    const int seg  = gw - row * WPR;

    const size_t base = (size_t)row * NV4;
    const float4* __restrict__ R = recon + base;
    const float4* __restrict__ X = xmat  + base;
    const float4* __restrict__ T = text  + base;
    const float4* __restrict__ C = rec   + base;

    float se0 = 0.f, se1 = 0.f, se2 = 0.f;
    float d0 = 0.f, d1 = 0.f, d2 = 0.f;
    float sx = 0.f;

    if (seg < 24) {
        // full 512-float4 segment: 8 unrolled pairs, 8 LDG.128 in flight
        int i = seg * SEG + lane;
        #pragma unroll 1
        for (int p = 0; p < 8; p++, i += 64) {
            float4 r0 = __ldcs(&R[i]);
            float4 x0 = __ldcs(&X[i]);
            float4 t0 = __ldcs(&T[i]);
            float4 c0 = __ldcs(&C[i]);
            float4 r1 = __ldcs(&R[i + 32]);
            float4 x1 = __ldcs(&X[i + 32]);
            float4 t1 = __ldcs(&T[i + 32]);
            float4 c1 = __ldcs(&C[i + 32]);

            se0 += sum_exp4(r0) + sum_exp4(r1);
            se1 += sum_exp4(t0) + sum_exp4(t1);
            se2 += sum_exp4(c0) + sum_exp4(c1);
            d0  += dot4(r0, x0) + dot4(r1, x1);
            d1  += dot4(t0, x0) + dot4(t1, x1);
            d2  += dot4(c0, x0) + dot4(c1, x1);
            sx  += x0.x + x0.y + x0.z + x0.w + x1.x + x1.y + x1.z + x1.w;
        }
    } else {
        // tail segment: columns [12288, 12500) = 212 float4
        for (int i = 24 * SEG + lane; i < NV4; i += 32) {
            float4 r0 = __ldcs(&R[i]);
            float4 x0 = __ldcs(&X[i]);
            float4 t0 = __ldcs(&T[i]);
            float4 c0 = __ldcs(&C[i]);
            se0 += sum_exp4(r0);
            se1 += sum_exp4(t0);
            se2 += sum_exp4(c0);
            d0  += dot4(r0, x0);
            d1  += dot4(t0, x0);
            d2  += dot4(c0, x0);
            sx  += x0.x + x0.y + x0.z + x0.w;
        }
    }

    // Warp reduce 7 scalars, one double atomicAdd each per warp (spread addrs).
    float vals[7] = {se0, se1, se2, d0, d1, d2, sx};
    #pragma unroll
    for (int j = 0; j < 7; j++) {
        float v = vals[j];
        #pragma unroll
        for (int o = 16; o > 0; o >>= 1) v += __shfl_down_sync(0xffffffffu, v, o);
        vals[j] = v;
    }
    if (lane == 0) {
        #pragma unroll
        for (int j = 0; j < 7; j++) atomicAdd(&g_row[row][j], (double)vals[j]);
    }
}

// Pass 2: 128 blocks x 256 threads. [B,D] dterms (2 float4/thread) +
// per-row BCE corrections (warp 0 of blocks 0..31). All partials go out as
// PLAIN STORES to staged arrays; only g_cnt is atomic. Last block warp-sums
// the staged partials and finalizes. Zero FP64 atomic serialization.
__global__ __launch_bounds__(P2_TPB)
void pass2_kernel(const float4* __restrict__ z,
                  const float4* __restrict__ mu,
                  const float4* __restrict__ lv,
                  const float4* __restrict__ pmu,
                  const float4* __restrict__ plv,
                  float* __restrict__ out)
{
    const int t    = threadIdx.x;
    const int lane = t & 31;
    const int w    = t >> 5;
    const int gtid = blockIdx.x * P2_TPB + t;
    const int NT   = P2_BLOCKS * P2_TPB;   // 32768 threads; n4 = 65536

    // ---- [B,D] elementwise terms: exactly 2 float4 per thread ----
    float k1 = 0.f, k2 = 0.f, wv = 0.f;
    #pragma unroll
    for (int rep = 0; rep < 2; rep++) {
        const int i = gtid + rep * NT;
        float4 m4  = mu[i];
        float4 l4  = lv[i];
        float4 pm4 = pmu[i];
        float4 pl4 = plv[i];
        float4 z4  = z[i];

        #pragma unroll
        for (int q = 0; q < 4; q++) {
            float m  = (&m4.x)[q];
            float l  = (&l4.x)[q];
            float pm = (&pm4.x)[q];
            float pl = (&pl4.x)[q];
            float zz = (&z4.x)[q];

            float el  = __expf(l);
            float epl = __expf(pl);

            k1 += 1.f + l - m * m - el;
            float dz = zz - pm;
            k2 += -0.5f * pl - 0.5f * dz * dz * __expf(-pl) + 0.5f * zz * zz;
            float dm = m - pm;
            wv += dm * dm + el + epl - 2.f * sqrtf(el * epl);
        }
    }

    __shared__ float sh[3][8];
    float vals[3] = {k1, k2, wv};
    #pragma unroll
    for (int j = 0; j < 3; j++) {
        float v = vals[j];
        #pragma unroll
        for (int o = 16; o > 0; o >>= 1) v += __shfl_down_sync(0xffffffffu, v, o);
        if (lane == 0) sh[j][w] = v;
    }
    __syncthreads();

    // ---- warp 0 (blocks 0..31): per-row BCE corrections, staged store ----
    if (w == 0 && blockIdx.x < 32) {
        const int row = blockIdx.x * 32 + lane;
        double se0 = g_row[row][0], se1 = g_row[row][1], se2 = g_row[row][2];
        double dd0 = g_row[row][3], dd1 = g_row[row][4], dd2 = g_row[row][5];
        double sxd = g_row[row][6];

        // logf on ~8e4-magnitude sums: ~1e-7 relative error, far < 1e-3.
        double c0 = dd0 - (double)logf((float)se0) * sxd;
        double c1 = dd1 - (double)logf((float)se1) * sxd;
        double c2 = dd2 - (double)logf((float)se2) * sxd;

        // reset this row's partials for the next graph replay
        #pragma unroll
        for (int j = 0; j < 7; j++) g_row[row][j] = 0.0;

        #pragma unroll
        for (int o = 16; o > 0; o >>= 1) {
            c0 += __shfl_down_sync(0xffffffffu, c0, o);
            c1 += __shfl_down_sync(0xffffffffu, c1, o);
            c2 += __shfl_down_sync(0xffffffffu, c2, o);
        }
        if (lane == 0) {
            g_fix[blockIdx.x][0] = c0;
            g_fix[blockIdx.x][1] = c1;
            g_fix[blockIdx.x][2] = c2;
        }
    }

    if (t == 0) {
        float s0 = 0.f, s1 = 0.f, s2 = 0.f;
        #pragma unroll
        for (int q = 0; q < 8; q++) { s0 += sh[0][q]; s1 += sh[1][q]; s2 += sh[2][q]; }
        g_dt[blockIdx.x][0] = (double)s0;
        g_dt[blockIdx.x][1] = (double)s1;
        g_dt[blockIdx.x][2] = (double)s2;
    }
    __syncthreads();   // g_fix store (warp 0) and g_dt store (t==0) both done

    // ---- completion protocol: one counter atomic per block ----
    __shared__ unsigned int s_done;
    if (t == 0) {
        __threadfence();
        s_done = (atomicAdd(&g_cnt, 1u) == P2_BLOCKS - 1) ? 1u : 0u;
    }
    __syncthreads();
    if (!s_done || w != 0) return;

    // ---- last block, warp 0: sum staged partials and finalize ----
    __threadfence();   // order counter observation before partial reads

    double a0 = 0.0, a1 = 0.0, a2 = 0.0;   // BCE corrections (32 entries)
    if (lane < 32) {
        a0 = g_fix[lane][0];
        a1 = g_fix[lane][1];
        a2 = g_fix[lane][2];
    }
    double s0 = 0.0, s1 = 0.0, s2 = 0.0;   // dterms (128 entries)
    for (int q = lane; q < P2_BLOCKS; q += 32) {
        s0 += g_dt[q][0];
        s1 += g_dt[q][1];
        s2 += g_dt[q][2];
    }
    #pragma unroll
    for (int o = 16; o > 0; o >>= 1) {
        a0 += __shfl_down_sync(0xffffffffu, a0, o);
        a1 += __shfl_down_sync(0xffffffffu, a1, o);
        a2 += __shfl_down_sync(0xffffffffu, a2, o);
        s0 += __shfl_down_sync(0xffffffffu, s0, o);
        s1 += __shfl_down_sync(0xffffffffu, s1, o);
        s2 += __shfl_down_sync(0xffffffffu, s2, o);
    }

    if (lane == 0) {
        const double invBN = 1.0 / ((double)B_ * (double)N_);
        const double invBD = 1.0 / ((double)B_ * (double)D_);

        double bce_merged = -a0 * invBN;
        double bce_text   = -a1 * invBN;
        double bce_rec    = -a2 * invBN;
        double BCE = (bce_merged + bce_text + bce_rec) / 3.0;

        double KLD1 = -0.5 * s0 * invBD;
        double KLD2 = s1 * invBD;            // ANNEAL = 1
        double wass = s2 / (double)B_;

        double lval = BCE + 0.5 * (KLD1 + KLD2) + wass;  // ANNEAL/2, EPSILON=1

        out[0] = (float)lval;
        out[1] = (float)BCE;
        out[2] = (float)wass;
        out[3] = (float)bce_rec;
        out[4] = (float)bce_text;
        out[5] = (float)bce_merged;

        g_cnt = 0u;   // reset for next graph replay
    }
}

extern "C" void kernel_launch(void* const* d_in, const int* in_sizes, int n_in,
                              void* d_out, int out_size) {
    const float* recon = (const float*)d_in[0];
    const float* x     = (const float*)d_in[1];
    const float* z     = (const float*)d_in[2];
    const float* mu    = (const float*)d_in[3];
    const float* lv    = (const float*)d_in[4];
    const float* text  = (const float*)d_in[5];
    const float* rec   = (const float*)d_in[6];
    const float* pmu   = (const float*)d_in[7];
    const float* plv   = (const float*)d_in[8];
    // d_in[9] = train_items, unused by the loss

    pass1_kernel<<<P1_GRID, P1_TPB>>>((const float4*)recon, (const float4*)x,
                                      (const float4*)text, (const float4*)rec);
    pass2_kernel<<<P2_BLOCKS, P2_TPB>>>((const float4*)z, (const float4*)mu,
                                        (const float4*)lv, (const float4*)pmu,
                                        (const float4*)plv, (float*)d_out);
}

// round 10
// speedup vs baseline: 1.0125x; 1.0125x over previous
#include <cuda_runtime.h>
#include <math.h>

#define B_ 1024
#define N_ 50000
#define D_ 256
#define NV4 (N_ / 4)        // 12500 float4 per row
#define WPR 25              // warps per row: 24 full segs of 512 + 1 seg of 212
#define SEG 512             // float4 per full warp segment
#define P1_TPB 256
#define P1_GRID (B_ * WPR / 8)   // 3200 blocks
#define P2_BLOCKS 128
#define P2_TPB 256
#define NBANK 8

// Per-row partials: 0..2 sumexp(merged,text,rec), 3..5 dot, 6 sum(x)
__device__ double g_row[B_][7];
// Banked dterm accumulators (atomicAdd; reset by final block)
__device__ double g_bank[NBANK][3];
// BCE correction partials, plain stores (overwritten each call -> no reset)
__device__ double g_fix[32][3];
__device__ unsigned int g_cnt;

__device__ __forceinline__ float sum_exp4(float4 v) {
    return __expf(v.x) + __expf(v.y) + __expf(v.z) + __expf(v.w);
}
__device__ __forceinline__ float dot4(float4 a, float4 b) {
    return a.x * b.x + a.y * b.y + a.z * b.z + a.w * b.w;
}

// Pass 1 (byte-identical to the proven round-3 kernel): warp-centric,
// barrier-free streaming reduce over the 3 logits matrices + x.
__global__ __launch_bounds__(P1_TPB, 4)
void pass1_kernel(const float4* __restrict__ recon,
                  const float4* __restrict__ xmat,
                  const float4* __restrict__ text,
                  const float4* __restrict__ rec)
{
    const int lane = threadIdx.x & 31;
    const int gw   = (blockIdx.x * P1_TPB + threadIdx.x) >> 5;  // global warp id
    const int row  = gw / WPR;
    const int seg  = gw - row * WPR;

    const size_t base = (size_t)row * NV4;
    const float4* __restrict__ R = recon + base;
    const float4* __restrict__ X = xmat  + base;
    const float4* __restrict__ T = text  + base;
    const float4* __restrict__ C = rec   + base;

    float se0 = 0.f, se1 = 0.f, se2 = 0.f;
    float d0 = 0.f, d1 = 0.f, d2 = 0.f;
    float sx = 0.f;

    if (seg < 24) {
        // full 512-float4 segment: 8 unrolled pairs, 8 LDG.128 in flight
        int i = seg * SEG + lane;
        #pragma unroll 1
        for (int p = 0; p < 8; p++, i += 64) {
            float4 r0 = __ldcs(&R[i]);
            float4 x0 = __ldcs(&X[i]);
            float4 t0 = __ldcs(&T[i]);
            float4 c0 = __ldcs(&C[i]);
            float4 r1 = __ldcs(&R[i + 32]);
            float4 x1 = __ldcs(&X[i + 32]);
            float4 t1 = __ldcs(&T[i + 32]);
            float4 c1 = __ldcs(&C[i + 32]);

            se0 += sum_exp4(r0) + sum_exp4(r1);
            se1 += sum_exp4(t0) + sum_exp4(t1);
            se2 += sum_exp4(c0) + sum_exp4(c1);
            d0  += dot4(r0, x0) + dot4(r1, x1);
            d1  += dot4(t0, x0) + dot4(t1, x1);
            d2  += dot4(c0, x0) + dot4(c1, x1);
            sx  += x0.x + x0.y + x0.z + x0.w + x1.x + x1.y + x1.z + x1.w;
        }
    } else {
        // tail segment: columns [12288, 12500) = 212 float4
        for (int i = 24 * SEG + lane; i < NV4; i += 32) {
            float4 r0 = __ldcs(&R[i]);
            float4 x0 = __ldcs(&X[i]);
            float4 t0 = __ldcs(&T[i]);
            float4 c0 = __ldcs(&C[i]);
            se0 += sum_exp4(r0);
            se1 += sum_exp4(t0);
            se2 += sum_exp4(c0);
            d0  += dot4(r0, x0);
            d1  += dot4(t0, x0);
            d2  += dot4(c0, x0);
            sx  += x0.x + x0.y + x0.z + x0.w;
        }
    }

    // Warp reduce 7 scalars, one double atomicAdd each per warp (spread addrs).
    float vals[7] = {se0, se1, se2, d0, d1, d2, sx};
    #pragma unroll
    for (int j = 0; j < 7; j++) {
        float v = vals[j];
        #pragma unroll
        for (int o = 16; o > 0; o >>= 1) v += __shfl_down_sync(0xffffffffu, v, o);
        vals[j] = v;
    }
    if (lane == 0) {
        #pragma unroll
        for (int j = 0; j < 7; j++) atomicAdd(&g_row[row][j], (double)vals[j]);
    }
}

// Pass 2: 128 blocks x 256 threads.
//  - warp 0 of blocks 0..31 issues its row's g_row loads FIRST (L2 latency
//    overlaps the dterm DRAM latency), computes BCE corrections, plain-stores
//    to g_fix.
//  - all threads do 2 float4 of [B,D] dterms; per-block partial goes to one
//    of 8 banked accumulators (max 16 serialized RMWs per address).
//  - last block (counter) sums 8+32 staged entries and finalizes.
__global__ __launch_bounds__(P2_TPB)
void pass2_kernel(const float4* __restrict__ z,
                  const float4* __restrict__ mu,
                  const float4* __restrict__ lv,
                  const float4* __restrict__ pmu,
                  const float4* __restrict__ plv,
                  float* __restrict__ out)
{
    const int t    = threadIdx.x;
    const int lane = t & 31;
    const int w    = t >> 5;
    const int bid  = blockIdx.x;
    const int gtid = bid * P2_TPB + t;
    const int NT   = P2_BLOCKS * P2_TPB;   // 32768 threads; n4 = 65536

    // ---- early-issue g_row loads for the correction path ----
    const bool fixer = (bid < 32) && (w == 0);
    double rse0 = 0.0, rse1 = 0.0, rse2 = 0.0;
    double rdd0 = 0.0, rdd1 = 0.0, rdd2 = 0.0, rsx = 0.0;
    const int row = bid * 32 + lane;
    if (fixer) {
        rse0 = g_row[row][0]; rse1 = g_row[row][1]; rse2 = g_row[row][2];
        rdd0 = g_row[row][3]; rdd1 = g_row[row][4]; rdd2 = g_row[row][5];
        rsx  = g_row[row][6];
    }

    // ---- [B,D] elementwise terms: exactly 2 float4 per thread ----
    float k1 = 0.f, k2 = 0.f, wv = 0.f;
    #pragma unroll
    for (int rep = 0; rep < 2; rep++) {
        const int i = gtid + rep * NT;
        float4 m4  = mu[i];
        float4 l4  = lv[i];
        float4 pm4 = pmu[i];
        float4 pl4 = plv[i];
        float4 z4  = z[i];

        #pragma unroll
        for (int q = 0; q < 4; q++) {
            float m  = (&m4.x)[q];
            float l  = (&l4.x)[q];
            float pm = (&pm4.x)[q];
            float pl = (&pl4.x)[q];
            float zz = (&z4.x)[q];

            float el  = __expf(l);
            float epl = __expf(pl);

            k1 += 1.f + l - m * m - el;
            float dz = zz - pm;
            k2 += -0.5f * pl - 0.5f * dz * dz * __expf(-pl) + 0.5f * zz * zz;
            float dm = m - pm;
            wv += dm * dm + el + epl - 2.f * sqrtf(el * epl);
        }
    }

    __shared__ float sh[3][8];
    float vals[3] = {k1, k2, wv};
    #pragma unroll
    for (int j = 0; j < 3; j++) {
        float v = vals[j];
        #pragma unroll
        for (int o = 16; o > 0; o >>= 1) v += __shfl_down_sync(0xffffffffu, v, o);
        if (lane == 0) sh[j][w] = v;
    }

    // ---- corrections (independent of smem reduce; data already in regs) ----
    if (fixer) {
        // logf on ~8e4-magnitude sums: ~1e-7 relative error, far < 1e-3.
        double c0 = rdd0 - (double)logf((float)rse0) * rsx;
        double c1 = rdd1 - (double)logf((float)rse1) * rsx;
        double c2 = rdd2 - (double)logf((float)rse2) * rsx;

        // reset this row's partials for the next graph replay
        #pragma unroll
        for (int j = 0; j < 7; j++) g_row[row][j] = 0.0;

        #pragma unroll
        for (int o = 16; o > 0; o >>= 1) {
            c0 += __shfl_down_sync(0xffffffffu, c0, o);
            c1 += __shfl_down_sync(0xffffffffu, c1, o);
            c2 += __shfl_down_sync(0xffffffffu, c2, o);
        }
        if (lane == 0) {
            g_fix[bid][0] = c0;
            g_fix[bid][1] = c1;
            g_fix[bid][2] = c2;
        }
    }

    __syncthreads();   // sh[][] ready

    if (t == 0) {
        float s0 = 0.f, s1 = 0.f, s2 = 0.f;
        #pragma unroll
        for (int q = 0; q < 8; q++) { s0 += sh[0][q]; s1 += sh[1][q]; s2 += sh[2][q]; }
        const int bk = bid & (NBANK - 1);
        atomicAdd(&g_bank[bk][0], (double)s0);
        atomicAdd(&g_bank[bk][1], (double)s1);
        atomicAdd(&g_bank[bk][2], (double)s2);
    }
    __syncthreads();   // g_fix store + bank atomics issued

    // ---- completion protocol: one counter atomic per block ----
    __shared__ unsigned int s_done;
    if (t == 0) {
        __threadfence();
        s_done = (atomicAdd(&g_cnt, 1u) == P2_BLOCKS - 1) ? 1u : 0u;
    }
    __syncthreads();
    if (!s_done || w != 0) return;

    // ---- last block, warp 0: sum staged partials and finalize ----
    __threadfence();   // order counter observation before partial reads

    double a0 = g_fix[lane][0];
    double a1 = g_fix[lane][1];
    double a2 = g_fix[lane][2];
    double s0 = 0.0, s1 = 0.0, s2 = 0.0;
    if (lane < NBANK) {
        s0 = g_bank[lane][0];
        s1 = g_bank[lane][1];
        s2 = g_bank[lane][2];
    }
    #pragma unroll
    for (int o = 16; o > 0; o >>= 1) {
        a0 += __shfl_down_sync(0xffffffffu, a0, o);
        a1 += __shfl_down_sync(0xffffffffu, a1, o);
        a2 += __shfl_down_sync(0xffffffffu, a2, o);
        s0 += __shfl_down_sync(0xffffffffu, s0, o);
        s1 += __shfl_down_sync(0xffffffffu, s1, o);
        s2 += __shfl_down_sync(0xffffffffu, s2, o);
    }

    // reset banks + counter for next graph replay
    if (lane < NBANK) {
        g_bank[lane][0] = 0.0;
        g_bank[lane][1] = 0.0;
        g_bank[lane][2] = 0.0;
    }

    if (lane == 0) {
        const double invBN = 1.0 / ((double)B_ * (double)N_);
        const double invBD = 1.0 / ((double)B_ * (double)D_);

        double bce_merged = -a0 * invBN;
        double bce_text   = -a1 * invBN;
        double bce_rec    = -a2 * invBN;
        double BCE = (bce_merged + bce_text + bce_rec) / 3.0;

        double KLD1 = -0.5 * s0 * invBD;
        double KLD2 = s1 * invBD;            // ANNEAL = 1
        double wass = s2 / (double)B_;

        double lval = BCE + 0.5 * (KLD1 + KLD2) + wass;  // ANNEAL/2, EPSILON=1

        out[0] = (float)lval;
        out[1] = (float)BCE;
        out[2] = (float)wass;
        out[3] = (float)bce_rec;
        out[4] = (float)bce_text;
        out[5] = (float)bce_merged;

        g_cnt = 0u;
    }
}

extern "C" void kernel_launch(void* const* d_in, const int* in_sizes, int n_in,
                              void* d_out, int out_size) {
    const float* recon = (const float*)d_in[0];
    const float* x     = (const float*)d_in[1];
    const float* z     = (const float*)d_in[2];
    const float* mu    = (const float*)d_in[3];
    const float* lv    = (const float*)d_in[4];
    const float* text  = (const float*)d_in[5];
    const float* rec   = (const float*)d_in[6];
    const float* pmu   = (const float*)d_in[7];
    const float* plv   = (const float*)d_in[8];
    // d_in[9] = train_items, unused by the loss

    pass1_kernel<<<P1_GRID, P1_TPB>>>((const float4*)recon, (const float4*)x,
                                      (const float4*)text, (const float4*)rec);
    pass2_kernel<<<P2_BLOCKS, P2_TPB>>>((const float4*)z, (const float4*)mu,
                                        (const float4*)lv, (const float4*)pmu,
                                        (const float4*)plv, (float*)d_out);
}

// round 11
// speedup vs baseline: 1.0290x; 1.0163x over previous
#include <cuda_runtime.h>
#include <math.h>

#define B_ 1024
#define N_ 50000
#define D_ 256
#define NV4 (N_ / 4)        // 12500 float4 per row
#define WPR 25              // warps per row: 24 full segs of 512 + 1 seg of 212
#define SEG 512             // float4 per full warp segment
#define P1_TPB 256
#define DT_BLOCKS 128       // dterm blocks prepended: bids [0, 128)
#define BCE_BLOCKS (B_ * WPR / 8)          // 3200 BCE blocks: bids [128, 3328)
#define P1_GRID (DT_BLOCKS + BCE_BLOCKS)   // 3328
#define NBANK 8
#define FX_BLOCKS 32

// Per-row partials: 0..2 sumexp(merged,text,rec), 3..5 dot, 6 sum(x)
__device__ double g_row[B_][7];
// Banked dterm accumulators (max 16 serialized RMWs per address)
__device__ double g_bank[NBANK][3];
// BCE correction sums
__device__ double g_acc[3];
__device__ unsigned int g_cnt;

__device__ __forceinline__ float sum_exp4(float4 v) {
    return __expf(v.x) + __expf(v.y) + __expf(v.z) + __expf(v.w);
}
__device__ __forceinline__ float dot4(float4 a, float4 b) {
    return a.x * b.x + a.y * b.y + a.z * b.z + a.w * b.w;
}

// Pass 1: bids [0,128) = [B,D] dterms (overlapped with the big stream);
// bids [128, 3328) = the proven warp-centric BCE streaming path, untouched.
__global__ __launch_bounds__(P1_TPB, 4)
void pass1_kernel(const float4* __restrict__ recon,
                  const float4* __restrict__ xmat,
                  const float4* __restrict__ text,
                  const float4* __restrict__ rec,
                  const float4* __restrict__ z,
                  const float4* __restrict__ mu,
                  const float4* __restrict__ lv,
                  const float4* __restrict__ pmu,
                  const float4* __restrict__ plv)
{
    const int lane = threadIdx.x & 31;

    if (blockIdx.x < DT_BLOCKS) {
        // ---- [B,D] elementwise terms: 2 float4 per thread ----
        const int t    = threadIdx.x;
        const int w    = t >> 5;
        const int gtid = blockIdx.x * P1_TPB + t;
        const int NT   = DT_BLOCKS * P1_TPB;   // 32768; n4 = 65536

        float k1 = 0.f, k2 = 0.f, wv = 0.f;
        #pragma unroll
        for (int rep = 0; rep < 2; rep++) {
            const int i = gtid + rep * NT;
            float4 m4  = mu[i];
            float4 l4  = lv[i];
            float4 pm4 = pmu[i];
            float4 pl4 = plv[i];
            float4 z4  = z[i];

            #pragma unroll
            for (int q = 0; q < 4; q++) {
                float m  = (&m4.x)[q];
                float l  = (&l4.x)[q];
                float pm = (&pm4.x)[q];
                float pl = (&pl4.x)[q];
                float zz = (&z4.x)[q];

                float el  = __expf(l);
                float epl = __expf(pl);

                k1 += 1.f + l - m * m - el;
                float dz = zz - pm;
                k2 += -0.5f * pl - 0.5f * dz * dz * __expf(-pl) + 0.5f * zz * zz;
                float dm = m - pm;
                wv += dm * dm + el + epl - 2.f * sqrtf(el * epl);
            }
        }

        __shared__ float sh[3][8];
        float vals[3] = {k1, k2, wv};
        #pragma unroll
        for (int j = 0; j < 3; j++) {
            float v = vals[j];
            #pragma unroll
            for (int o = 16; o > 0; o >>= 1) v += __shfl_down_sync(0xffffffffu, v, o);
            if (lane == 0) sh[j][w] = v;
        }
        __syncthreads();

        if (t == 0) {
            float s0 = 0.f, s1 = 0.f, s2 = 0.f;
            #pragma unroll
            for (int q = 0; q < 8; q++) { s0 += sh[0][q]; s1 += sh[1][q]; s2 += sh[2][q]; }
            const int bk = blockIdx.x & (NBANK - 1);
            atomicAdd(&g_bank[bk][0], (double)s0);
            atomicAdd(&g_bank[bk][1], (double)s1);
            atomicAdd(&g_bank[bk][2], (double)s2);
        }
        return;
    }

    // ---- BCE streaming (hot path, byte-identical logic) ----
    const int gw   = ((blockIdx.x - DT_BLOCKS) * P1_TPB + threadIdx.x) >> 5;
    const int row  = gw / WPR;
    const int seg  = gw - row * WPR;

    const size_t base = (size_t)row * NV4;
    const float4* __restrict__ R = recon + base;
    const float4* __restrict__ X = xmat  + base;
    const float4* __restrict__ T = text  + base;
    const float4* __restrict__ C = rec   + base;

    float se0 = 0.f, se1 = 0.f, se2 = 0.f;
    float d0 = 0.f, d1 = 0.f, d2 = 0.f;
    float sx = 0.f;

    if (seg < 24) {
        // full 512-float4 segment: 8 unrolled pairs, 8 LDG.128 in flight
        int i = seg * SEG + lane;
        #pragma unroll 1
        for (int p = 0; p < 8; p++, i += 64) {
            float4 r0 = __ldcs(&R[i]);
            float4 x0 = __ldcs(&X[i]);
            float4 t0 = __ldcs(&T[i]);
            float4 c0 = __ldcs(&C[i]);
            float4 r1 = __ldcs(&R[i + 32]);
            float4 x1 = __ldcs(&X[i + 32]);
            float4 t1 = __ldcs(&T[i + 32]);
            float4 c1 = __ldcs(&C[i + 32]);

            se0 += sum_exp4(r0) + sum_exp4(r1);
            se1 += sum_exp4(t0) + sum_exp4(t1);
            se2 += sum_exp4(c0) + sum_exp4(c1);
            d0  += dot4(r0, x0) + dot4(r1, x1);
            d1  += dot4(t0, x0) + dot4(t1, x1);
            d2  += dot4(c0, x0) + dot4(c1, x1);
            sx  += x0.x + x0.y + x0.z + x0.w + x1.x + x1.y + x1.z + x1.w;
        }
    } else {
        // tail segment: columns [12288, 12500) = 212 float4
        for (int i = 24 * SEG + lane; i < NV4; i += 32) {
            float4 r0 = __ldcs(&R[i]);
            float4 x0 = __ldcs(&X[i]);
            float4 t0 = __ldcs(&T[i]);
            float4 c0 = __ldcs(&C[i]);
            se0 += sum_exp4(r0);
            se1 += sum_exp4(t0);
            se2 += sum_exp4(c0);
            d0  += dot4(r0, x0);
            d1  += dot4(t0, x0);
            d2  += dot4(c0, x0);
            sx  += x0.x + x0.y + x0.z + x0.w;
        }
    }

    // Warp reduce 7 scalars, one double atomicAdd each per warp (spread addrs).
    float vals[7] = {se0, se1, se2, d0, d1, d2, sx};
    #pragma unroll
    for (int j = 0; j < 7; j++) {
        float v = vals[j];
        #pragma unroll
        for (int o = 16; o > 0; o >>= 1) v += __shfl_down_sync(0xffffffffu, v, o);
        vals[j] = v;
    }
    if (lane == 0) {
        #pragma unroll
        for (int j = 0; j < 7; j++) atomicAdd(&g_row[row][j], (double)vals[j]);
    }
}

// Fixup: 32 blocks x 1 warp. Per-row BCE corrections + finalize.
__global__ __launch_bounds__(32)
void fixup_kernel(float* __restrict__ out)
{
    const int lane = threadIdx.x;
    const int row  = blockIdx.x * 32 + lane;

    double se0 = g_row[row][0], se1 = g_row[row][1], se2 = g_row[row][2];
    double dd0 = g_row[row][3], dd1 = g_row[row][4], dd2 = g_row[row][5];
    double sxd = g_row[row][6];

    // logf on ~8e4-magnitude sums: ~1e-7 relative error, far < 1e-3.
    double c0 = dd0 - (double)logf((float)se0) * sxd;
    double c1 = dd1 - (double)logf((float)se1) * sxd;
    double c2 = dd2 - (double)logf((float)se2) * sxd;

    // reset this row's partials for the next graph replay
    #pragma unroll
    for (int j = 0; j < 7; j++) g_row[row][j] = 0.0;

    #pragma unroll
    for (int o = 16; o > 0; o >>= 1) {
        c0 += __shfl_down_sync(0xffffffffu, c0, o);
        c1 += __shfl_down_sync(0xffffffffu, c1, o);
        c2 += __shfl_down_sync(0xffffffffu, c2, o);
    }

    unsigned last = 0;
    if (lane == 0) {
        atomicAdd(&g_acc[0], c0);
        atomicAdd(&g_acc[1], c1);
        atomicAdd(&g_acc[2], c2);
        __threadfence();
        last = (atomicAdd(&g_cnt, 1u) == FX_BLOCKS - 1) ? 1u : 0u;
    }
    last = __shfl_sync(0xffffffffu, last, 0);
    if (!last) return;

    __threadfence();   // order counter observation before partial reads

    // warp-cooperative sum of the 8 banked dterm accumulators
    double s0 = 0.0, s1 = 0.0, s2 = 0.0;
    if (lane < NBANK) {
        s0 = g_bank[lane][0];
        s1 = g_bank[lane][1];
        s2 = g_bank[lane][2];
        g_bank[lane][0] = 0.0;   // reset for next replay
        g_bank[lane][1] = 0.0;
        g_bank[lane][2] = 0.0;
    }
    #pragma unroll
    for (int o = 16; o > 0; o >>= 1) {
        s0 += __shfl_down_sync(0xffffffffu, s0, o);
        s1 += __shfl_down_sync(0xffffffffu, s1, o);
        s2 += __shfl_down_sync(0xffffffffu, s2, o);
    }

    if (lane == 0) {
        double a0 = atomicAdd(&g_acc[0], 0.0);
        double a1 = atomicAdd(&g_acc[1], 0.0);
        double a2 = atomicAdd(&g_acc[2], 0.0);

        const double invBN = 1.0 / ((double)B_ * (double)N_);
        const double invBD = 1.0 / ((double)B_ * (double)D_);

        double bce_merged = -a0 * invBN;
        double bce_text   = -a1 * invBN;
        double bce_rec    = -a2 * invBN;
        double BCE = (bce_merged + bce_text + bce_rec) / 3.0;

        double KLD1 = -0.5 * s0 * invBD;
        double KLD2 = s1 * invBD;            // ANNEAL = 1
        double wass = s2 / (double)B_;

        double lval = BCE + 0.5 * (KLD1 + KLD2) + wass;  // ANNEAL/2, EPSILON=1

        out[0] = (float)lval;
        out[1] = (float)BCE;
        out[2] = (float)wass;
        out[3] = (float)bce_rec;
        out[4] = (float)bce_text;
        out[5] = (float)bce_merged;

        g_acc[0] = 0.0; g_acc[1] = 0.0; g_acc[2] = 0.0;
        g_cnt = 0u;
    }
}

extern "C" void kernel_launch(void* const* d_in, const int* in_sizes, int n_in,
                              void* d_out, int out_size) {
    const float* recon = (const float*)d_in[0];
    const float* x     = (const float*)d_in[1];
    const float* z     = (const float*)d_in[2];
    const float* mu    = (const float*)d_in[3];
    const float* lv    = (const float*)d_in[4];
    const float* text  = (const float*)d_in[5];
    const float* rec   = (const float*)d_in[6];
    const float* pmu   = (const float*)d_in[7];
    const float* plv   = (const float*)d_in[8];
    // d_in[9] = train_items, unused by the loss

    pass1_kernel<<<P1_GRID, P1_TPB>>>((const float4*)recon, (const float4*)x,
                                      (const float4*)text, (const float4*)rec,
                                      (const float4*)z, (const float4*)mu,
                                      (const float4*)lv, (const float4*)pmu,
                                      (const float4*)plv);
    fixup_kernel<<<FX_BLOCKS, 32>>>((float*)d_out);
}

// round 12
// speedup vs baseline: 1.0311x; 1.0020x over previous
#include <cuda_runtime.h>
#include <math.h>

#define B_ 1024
#define N_ 50000
#define D_ 256
#define NV4 (N_ / 4)        // 12500 float4 per row
#define WPR 25              // warps per row: 24 full segs of 512 + 1 seg of 212
#define SEG 512             // float4 per full warp segment
#define P1_TPB 256
#define DT_BLOCKS 128       // dterm blocks prepended: bids [0, 128)
#define BCE_BLOCKS (B_ * WPR / 8)          // 3200 BCE blocks: bids [128, 3328)
#define P1_GRID (DT_BLOCKS + BCE_BLOCKS)   // 3328
#define NBANK 8
#define FX_BLOCKS 4
#define FX_TPB 256

// Per-row partials padded to 8 doubles (64B) for vector loads/stores:
// 0..2 sumexp(merged,text,rec), 3..5 dot, 6 sum(x), 7 pad
__device__ double g_row[B_][8];
// Banked dterm accumulators (max 16 serialized RMWs per address)
__device__ double g_bank[NBANK][3];
// BCE correction sums
__device__ double g_acc[3];
__device__ unsigned int g_cnt;

__device__ __forceinline__ float sum_exp4(float4 v) {
    return __expf(v.x) + __expf(v.y) + __expf(v.z) + __expf(v.w);
}
__device__ __forceinline__ float dot4(float4 a, float4 b) {
    return a.x * b.x + a.y * b.y + a.z * b.z + a.w * b.w;
}

// Pass 1: bids [0,128) = [B,D] dterms (overlapped with the big stream);
// bids [128, 3328) = the proven warp-centric BCE streaming path, untouched.
__global__ __launch_bounds__(P1_TPB, 4)
void pass1_kernel(const float4* __restrict__ recon,
                  const float4* __restrict__ xmat,
                  const float4* __restrict__ text,
                  const float4* __restrict__ rec,
                  const float4* __restrict__ z,
                  const float4* __restrict__ mu,
                  const float4* __restrict__ lv,
                  const float4* __restrict__ pmu,
                  const float4* __restrict__ plv)
{
    const int lane = threadIdx.x & 31;

    if (blockIdx.x < DT_BLOCKS) {
        // ---- [B,D] elementwise terms: 2 float4 per thread ----
        const int t    = threadIdx.x;
        const int w    = t >> 5;
        const int gtid = blockIdx.x * P1_TPB + t;
        const int NT   = DT_BLOCKS * P1_TPB;   // 32768; n4 = 65536

        float k1 = 0.f, k2 = 0.f, wv = 0.f;
        #pragma unroll
        for (int rep = 0; rep < 2; rep++) {
            const int i = gtid + rep * NT;
            float4 m4  = mu[i];
            float4 l4  = lv[i];
            float4 pm4 = pmu[i];
            float4 pl4 = plv[i];
            float4 z4  = z[i];

            #pragma unroll
            for (int q = 0; q < 4; q++) {
                float m  = (&m4.x)[q];
                float l  = (&l4.x)[q];
                float pm = (&pm4.x)[q];
                float pl = (&pl4.x)[q];
                float zz = (&z4.x)[q];

                float el  = __expf(l);
                float epl = __expf(pl);

                k1 += 1.f + l - m * m - el;
                float dz = zz - pm;
                k2 += -0.5f * pl - 0.5f * dz * dz * __expf(-pl) + 0.5f * zz * zz;
                float dm = m - pm;
                wv += dm * dm + el + epl - 2.f * sqrtf(el * epl);
            }
        }

        __shared__ float sh[3][8];
        float vals[3] = {k1, k2, wv};
        #pragma unroll
        for (int j = 0; j < 3; j++) {
            float v = vals[j];
            #pragma unroll
            for (int o = 16; o > 0; o >>= 1) v += __shfl_down_sync(0xffffffffu, v, o);
            if (lane == 0) sh[j][w] = v;
        }
        __syncthreads();

        if (t == 0) {
            float s0 = 0.f, s1 = 0.f, s2 = 0.f;
            #pragma unroll
            for (int q = 0; q < 8; q++) { s0 += sh[0][q]; s1 += sh[1][q]; s2 += sh[2][q]; }
            const int bk = blockIdx.x & (NBANK - 1);
            atomicAdd(&g_bank[bk][0], (double)s0);
            atomicAdd(&g_bank[bk][1], (double)s1);
            atomicAdd(&g_bank[bk][2], (double)s2);
        }
        return;
    }

    // ---- BCE streaming (hot path, byte-identical logic) ----
    const int gw   = ((blockIdx.x - DT_BLOCKS) * P1_TPB + threadIdx.x) >> 5;
    const int row  = gw / WPR;
    const int seg  = gw - row * WPR;

    const size_t base = (size_t)row * NV4;
    const float4* __restrict__ R = recon + base;
    const float4* __restrict__ X = xmat  + base;
    const float4* __restrict__ T = text  + base;
    const float4* __restrict__ C = rec   + base;

    float se0 = 0.f, se1 = 0.f, se2 = 0.f;
    float d0 = 0.f, d1 = 0.f, d2 = 0.f;
    float sx = 0.f;

    if (seg < 24) {
        // full 512-float4 segment: 8 unrolled pairs, 8 LDG.128 in flight
        int i = seg * SEG + lane;
        #pragma unroll 1
        for (int p = 0; p < 8; p++, i += 64) {
            float4 r0 = __ldcs(&R[i]);
            float4 x0 = __ldcs(&X[i]);
            float4 t0 = __ldcs(&T[i]);
            float4 c0 = __ldcs(&C[i]);
            float4 r1 = __ldcs(&R[i + 32]);
            float4 x1 = __ldcs(&X[i + 32]);
            float4 t1 = __ldcs(&T[i + 32]);
            float4 c1 = __ldcs(&C[i + 32]);

            se0 += sum_exp4(r0) + sum_exp4(r1);
            se1 += sum_exp4(t0) + sum_exp4(t1);
            se2 += sum_exp4(c0) + sum_exp4(c1);
            d0  += dot4(r0, x0) + dot4(r1, x1);
            d1  += dot4(t0, x0) + dot4(t1, x1);
            d2  += dot4(c0, x0) + dot4(c1, x1);
            sx  += x0.x + x0.y + x0.z + x0.w + x1.x + x1.y + x1.z + x1.w;
        }
    } else {
        // tail segment: columns [12288, 12500) = 212 float4
        for (int i = 24 * SEG + lane; i < NV4; i += 32) {
            float4 r0 = __ldcs(&R[i]);
            float4 x0 = __ldcs(&X[i]);
            float4 t0 = __ldcs(&T[i]);
            float4 c0 = __ldcs(&C[i]);
            se0 += sum_exp4(r0);
            se1 += sum_exp4(t0);
            se2 += sum_exp4(c0);
            d0  += dot4(r0, x0);
            d1  += dot4(t0, x0);
            d2  += dot4(c0, x0);
            sx  += x0.x + x0.y + x0.z + x0.w;
        }
    }

    // Warp reduce 7 scalars, one double atomicAdd each per warp (spread addrs).
    float vals[7] = {se0, se1, se2, d0, d1, d2, sx};
    #pragma unroll
    for (int j = 0; j < 7; j++) {
        float v = vals[j];
        #pragma unroll
        for (int o = 16; o > 0; o >>= 1) v += __shfl_down_sync(0xffffffffu, v, o);
        vals[j] = v;
    }
    if (lane == 0) {
        #pragma unroll
        for (int j = 0; j < 7; j++) atomicAdd(&g_row[row][j], (double)vals[j]);
    }
}

// Fixup: 4 blocks x 256 threads, 1 row per thread. Float correction math;
// doubles only at partial-sum level. Counter protocol, last block finalizes.
__global__ __launch_bounds__(FX_TPB)
void fixup_kernel(float* __restrict__ out)
{
    const int t    = threadIdx.x;
    const int lane = t & 31;
    const int w    = t >> 5;
    const int row  = blockIdx.x * FX_TPB + t;

    // vectorized row load: 4 x double2 (LDG.128)
    const double2* rp = reinterpret_cast<const double2*>(&g_row[row][0]);
    double2 v0 = rp[0];   // se0, se1
    double2 v1 = rp[1];   // se2, dd0
    double2 v2 = rp[2];   // dd1, dd2
    double2 v3 = rp[3];   // sx, pad

    // float correction math: |c| ~ 2.8e5, budget ~2.9e5 abs on the sum -> safe.
    float sxf = (float)v3.x;
    float c0 = (float)v1.y - logf((float)v0.x) * sxf;
    float c1 = (float)v2.x - logf((float)v0.y) * sxf;
    float c2 = (float)v2.y - logf((float)v1.x) * sxf;

    // reset this row for next graph replay (4 x STG.128)
    double2* wp = reinterpret_cast<double2*>(&g_row[row][0]);
    double2 zz2; zz2.x = 0.0; zz2.y = 0.0;
    wp[0] = zz2; wp[1] = zz2; wp[2] = zz2; wp[3] = zz2;

    // warp reduce floats, then block-level double partials
    #pragma unroll
    for (int o = 16; o > 0; o >>= 1) {
        c0 += __shfl_down_sync(0xffffffffu, c0, o);
        c1 += __shfl_down_sync(0xffffffffu, c1, o);
        c2 += __shfl_down_sync(0xffffffffu, c2, o);
    }

    __shared__ double sh[3][8];
    if (lane == 0) {
        sh[0][w] = (double)c0;
        sh[1][w] = (double)c1;
        sh[2][w] = (double)c2;
    }
    __syncthreads();

    __shared__ unsigned int s_done;
    if (t == 0) {
        double a0 = 0.0, a1 = 0.0, a2 = 0.0;
        #pragma unroll
        for (int q = 0; q < 8; q++) { a0 += sh[0][q]; a1 += sh[1][q]; a2 += sh[2][q]; }
        atomicAdd(&g_acc[0], a0);
        atomicAdd(&g_acc[1], a1);
        atomicAdd(&g_acc[2], a2);
        __threadfence();
        s_done = (atomicAdd(&g_cnt, 1u) == FX_BLOCKS - 1) ? 1u : 0u;
    }
    __syncthreads();
    if (!s_done || w != 0) return;

    // ---- last block, warp 0: finalize ----
    __threadfence();

    double s0 = 0.0, s1 = 0.0, s2 = 0.0;
    if (lane < NBANK) {
        s0 = g_bank[lane][0];
        s1 = g_bank[lane][1];
        s2 = g_bank[lane][2];
        g_bank[lane][0] = 0.0;   // reset for next replay
        g_bank[lane][1] = 0.0;
        g_bank[lane][2] = 0.0;
    }
    #pragma unroll
    for (int o = 16; o > 0; o >>= 1) {
        s0 += __shfl_down_sync(0xffffffffu, s0, o);
        s1 += __shfl_down_sync(0xffffffffu, s1, o);
        s2 += __shfl_down_sync(0xffffffffu, s2, o);
    }

    if (lane == 0) {
        double a0 = atomicAdd(&g_acc[0], 0.0);
        double a1 = atomicAdd(&g_acc[1], 0.0);
        double a2 = atomicAdd(&g_acc[2], 0.0);

        const double invBN = 1.0 / ((double)B_ * (double)N_);
        const double invBD = 1.0 / ((double)B_ * (double)D_);

        double bce_merged = -a0 * invBN;
        double bce_text   = -a1 * invBN;
        double bce_rec    = -a2 * invBN;
        double BCE = (bce_merged + bce_text + bce_rec) / 3.0;

        double KLD1 = -0.5 * s0 * invBD;
        double KLD2 = s1 * invBD;            // ANNEAL = 1
        double wass = s2 / (double)B_;

        double lval = BCE + 0.5 * (KLD1 + KLD2) + wass;  // ANNEAL/2, EPSILON=1

        out[0] = (float)lval;
        out[1] = (float)BCE;
        out[2] = (float)wass;
        out[3] = (float)bce_rec;
        out[4] = (float)bce_text;
        out[5] = (float)bce_merged;

        g_acc[0] = 0.0; g_acc[1] = 0.0; g_acc[2] = 0.0;
        g_cnt = 0u;
    }
}

extern "C" void kernel_launch(void* const* d_in, const int* in_sizes, int n_in,
                              void* d_out, int out_size) {
    const float* recon = (const float*)d_in[0];
    const float* x     = (const float*)d_in[1];
    const float* z     = (const float*)d_in[2];
    const float* mu    = (const float*)d_in[3];
    const float* lv    = (const float*)d_in[4];
    const float* text  = (const float*)d_in[5];
    const float* rec   = (const float*)d_in[6];
    const float* pmu   = (const float*)d_in[7];
    const float* plv   = (const float*)d_in[8];
    // d_in[9] = train_items, unused by the loss

    pass1_kernel<<<P1_GRID, P1_TPB>>>((const float4*)recon, (const float4*)x,
                                      (const float4*)text, (const float4*)rec,
                                      (const float4*)z, (const float4*)mu,
                                      (const float4*)lv, (const float4*)pmu,
                                      (const float4*)plv);
    fixup_kernel<<<FX_BLOCKS, FX_TPB>>>((float*)d_out);
}